// round 15
// baseline (speedup 1.0000x reference)
#include <cuda_runtime.h>
#include <math_constants.h>
#include <cstdint>
#include <cstddef>

#define BATCH 2
#define NPT   4096
#define NB    (BATCH * NPT)
#define KNN   20
#define TCAP  512

// ---------------- scratch (device globals; no allocation) ----------------
__device__ float g_dist[(size_t)NB * NPT];     // 134 MB distance matrix (reused per layer)
__device__ int   g_idx[NB * KNN];
__device__ float g_xx[NB];
__device__ float g_xcat[(size_t)NB * 512];     // x1|x2|x3|x4 at channel offsets 0/64/128/256
__device__ float g_base[(size_t)NB * 256];
__device__ float g_Wc[256 * 128];
__device__ float g_act[(size_t)NB * 1024];
__device__ float g_gvec[BATCH * 1024];
__device__ float g_sterm[BATCH * 512];
__device__ float g_h1[(size_t)NB * 512];
__device__ float g_h2[(size_t)NB * 256];

// ---------------- packed f32x2 helpers (sm_103a FFMA2) ----------------
__device__ __forceinline__ unsigned long long pk2(float x) {
    unsigned long long r;
    asm("mov.b64 %0, {%1, %1};" : "=l"(r) : "f"(x));
    return r;
}
__device__ __forceinline__ void fma2(unsigned long long& c, unsigned long long a,
                                     unsigned long long b) {
    asm("fma.rn.f32x2 %0, %1, %2, %0;" : "+l"(c) : "l"(a), "l"(b));
}
__device__ __forceinline__ float2 upk2(unsigned long long v) {
    float2 r;
    asm("mov.b64 {%0, %1}, %2;" : "=f"(r.x), "=f"(r.y) : "l"(v));
    return r;
}

// ---------------- squared norms ----------------
__global__ void k_sqnorm(const float* __restrict__ X, int rs, int C, float* __restrict__ xx) {
    int i = blockIdx.x * blockDim.x + threadIdx.x;
    if (i >= NB) return;
    const float* r = X + (size_t)i * rs;
    float s = 0.f;
    for (int c = 0; c < C; c++) s = fmaf(r[c], r[c], s);
    xx[i] = s;
}

// ---------------- pairwise distance: symmetric tiles, double-buffered smem, FFMA2 ------
// grid (NPT/128, NPT/128, B), block 256; FMA chain bit-identical to round-13.
__global__ void __launch_bounds__(256)
k_dist(const float* __restrict__ X, int rs, int C,
       const float* __restrict__ xx, float* __restrict__ D) {
    if (blockIdx.y < blockIdx.x) return;   // lower triangle via mirror
    int m0 = blockIdx.x * 128;
    int n0 = blockIdx.y * 128;
    int b  = blockIdx.z;
    const float* Xb  = X  + (size_t)b * NPT * rs;
    const float* xxb = xx + b * NPT;
    __shared__ float sA[2][16][132];
    __shared__ float sB[2][16][132];
    unsigned long long acc2[8][4];
#pragma unroll
    for (int i = 0; i < 8; i++)
#pragma unroll
        for (int j = 0; j < 4; j++) acc2[i][j] = 0ull;
    int t = threadIdx.x;
    int mi = t & 15, nj = t >> 4;
    int lrow = t >> 1, lk = (t & 1) * 8;
    const float* arow = Xb + (size_t)(m0 + lrow) * rs + lk;
    const float* brow = Xb + (size_t)(n0 + lrow) * rs + lk;

    float rA[8], rB[8];
#pragma unroll
    for (int q = 0; q < 8; q++) {            // prologue: chunk k0=0
        bool ok = (lk + q) < C;
        rA[q] = ok ? arow[q] : 0.f;
        rB[q] = ok ? brow[q] : 0.f;
    }
    int p = 0;
    for (int k0 = 0; k0 < C; k0 += 16, p ^= 1) {
#pragma unroll
        for (int q = 0; q < 8; q++) {
            sA[p][lk + q][lrow] = rA[q];
            sB[p][lk + q][lrow] = rB[q];
        }
        __syncthreads();
        int kn = k0 + 16;
        if (kn < C) {                        // prefetch next chunk during compute
#pragma unroll
            for (int q = 0; q < 8; q++) {
                bool ok = (kn + lk + q) < C;
                rA[q] = ok ? arow[kn + q] : 0.f;
                rB[q] = ok ? brow[kn + q] : 0.f;
            }
        }
#pragma unroll
        for (int kk = 0; kk < 16; kk++) {
            float4 a0 = *(const float4*)&sA[p][kk][mi * 4];
            float4 a1 = *(const float4*)&sA[p][kk][64 + mi * 4];
            unsigned long long bp[4];
            bp[0] = *(const unsigned long long*)&sB[p][kk][nj * 4];
            bp[1] = *(const unsigned long long*)&sB[p][kk][nj * 4 + 2];
            bp[2] = *(const unsigned long long*)&sB[p][kk][64 + nj * 4];
            bp[3] = *(const unsigned long long*)&sB[p][kk][64 + nj * 4 + 2];
            float av[8] = {a0.x, a0.y, a0.z, a0.w, a1.x, a1.y, a1.z, a1.w};
#pragma unroll
            for (int i = 0; i < 8; i++) {
                unsigned long long ai = pk2(av[i]);
#pragma unroll
                for (int jp = 0; jp < 4; jp++) fma2(acc2[i][jp], ai, bp[jp]);
            }
        }
    }
    float accf[8][8];
#pragma unroll
    for (int i = 0; i < 8; i++)
#pragma unroll
        for (int jp = 0; jp < 4; jp++) {
            float2 f = upk2(acc2[i][jp]);
            accf[i][jp * 2] = f.x;
            accf[i][jp * 2 + 1] = f.y;
        }
    // normal tile store
#pragma unroll
    for (int ih = 0; ih < 2; ih++)
#pragma unroll
        for (int i = 0; i < 4; i++) {
            int ig = m0 + ih * 64 + mi * 4 + i;
            float xi = xxb[ig];
            float* dst = D + ((size_t)b * NPT + ig) * NPT;
#pragma unroll
            for (int jh = 0; jh < 2; jh++) {
                int j0 = n0 + jh * 64 + nj * 4;
                float4 xj = *(const float4*)&xxb[j0];
                float4 v;
                v.x = xi + xj.x - 2.f * accf[ih * 4 + i][jh * 4 + 0];
                v.y = xi + xj.y - 2.f * accf[ih * 4 + i][jh * 4 + 1];
                v.z = xi + xj.z - 2.f * accf[ih * 4 + i][jh * 4 + 2];
                v.w = xi + xj.w - 2.f * accf[ih * 4 + i][jh * 4 + 3];
                *(float4*)(dst + j0) = v;
            }
        }
    // mirrored tile store (off-diagonal blocks only); bitwise-identical by commutativity
    if (blockIdx.y > blockIdx.x) {
#pragma unroll
        for (int jh = 0; jh < 2; jh++)
#pragma unroll
            for (int c = 0; c < 4; c++) {
                int jg = n0 + jh * 64 + nj * 4 + c;
                float xj = xxb[jg];
                float* dst = D + ((size_t)b * NPT + jg) * NPT;
#pragma unroll
                for (int ih = 0; ih < 2; ih++) {
                    int i0 = m0 + ih * 64 + mi * 4;
                    float4 xi4 = *(const float4*)&xxb[i0];
                    float4 v;
                    v.x = xj + xi4.x - 2.f * accf[ih * 4 + 0][jh * 4 + c];
                    v.y = xj + xi4.y - 2.f * accf[ih * 4 + 1][jh * 4 + c];
                    v.z = xj + xi4.z - 2.f * accf[ih * 4 + 2][jh * 4 + c];
                    v.w = xj + xi4.w - 2.f * accf[ih * 4 + 3][jh * 4 + c];
                    *(float4*)(dst + i0) = v;
                }
            }
    }
}

// ---------------- threshold-filtered exact top-20 smallest (stable ties) ----------------
// float4 scan; candidate buffer kept in ascending-j order via warp prefix-sum so the
// selected index set is identical to the scalar version.
__global__ void k_topk(const float* __restrict__ D, int* __restrict__ outp) {
    __shared__ float sVal[8][TCAP];
    __shared__ int   sInd[8][TCAP];
    int w    = threadIdx.x >> 5;
    int row  = blockIdx.x * 8 + w;
    int lane = threadIdx.x & 31;
    const float* d = D + (size_t)row * NPT;

    // ---- pass 1: threshold = 20th smallest of first 256 (float4 sample) ----
    float sd[8];
#pragma unroll
    for (int p = 0; p < 8; p++) sd[p] = CUDART_INF_F;
#pragma unroll
    for (int q = 0; q < 2; q++) {
        float4 v4 = *(const float4*)(d + lane * 4 + q * 128);
        float vv[4] = {v4.x, v4.y, v4.z, v4.w};
#pragma unroll
        for (int e = 0; e < 4; e++) {
            float cd = vv[e];
#pragma unroll
            for (int p = 0; p < 8; p++) {
                if (cd < sd[p]) { float tm = sd[p]; sd[p] = cd; cd = tm; }
            }
        }
    }
    float t = CUDART_INF_F;
#pragma unroll 1
    for (int r = 0; r < KNN; r++) {
        float cd = sd[0]; int cl = lane;
#pragma unroll
        for (int off = 16; off > 0; off >>= 1) {
            float od = __shfl_xor_sync(0xffffffffu, cd, off);
            int   ol = __shfl_xor_sync(0xffffffffu, cl, off);
            if (od < cd || (od == cd && ol < cl)) { cd = od; cl = ol; }
        }
        if (lane == cl) {
#pragma unroll
            for (int p = 0; p < 7; p++) sd[p] = sd[p + 1];
            sd[7] = CUDART_INF_F;
        }
        t = cd;
    }

    // ---- pass 2: float4 scan, compact v<=t in ascending-j order ----
    int cnt = 0;
#pragma unroll 1
    for (int j0 = lane * 4; j0 < NPT; j0 += 128) {
        float4 v4 = *(const float4*)(d + j0);
        float vv[4] = {v4.x, v4.y, v4.z, v4.w};
        bool pr[4];
        int nl = 0;
#pragma unroll
        for (int e = 0; e < 4; e++) { pr[e] = (vv[e] <= t); nl += pr[e]; }
        int sc = nl;
#pragma unroll
        for (int off = 1; off < 32; off <<= 1) {
            int o = __shfl_up_sync(0xffffffffu, sc, off);
            if (lane >= off) sc += o;
        }
        int total = __shfl_sync(0xffffffffu, sc, 31);
        int pos = cnt + sc - nl;   // exclusive prefix: ascending (lane, e) = ascending j
#pragma unroll
        for (int e = 0; e < 4; e++) {
            if (pr[e]) {
                if (pos < TCAP) { sVal[w][pos] = vv[e]; sInd[w][pos] = j0 + e; }
                pos++;
            }
        }
        cnt += total;
    }

    // ---- pass 3: exact stable top-20 ----
    float dist[KNN]; int ind[KNN];
#pragma unroll
    for (int p = 0; p < KNN; p++) { dist[p] = CUDART_INF_F; ind[p] = 0x7fffffff; }
    if (cnt <= TCAP) {
        for (int i = lane; i < cnt; i += 32) {
            float v = sVal[w][i];
            if (v < dist[KNN - 1]) {
                float cd = v; int ci = sInd[w][i];
#pragma unroll
                for (int p = 0; p < KNN; p++) {
                    if (cd < dist[p]) {
                        float td = dist[p]; int ti = ind[p];
                        dist[p] = cd; ind[p] = ci; cd = td; ci = ti;
                    }
                }
            }
        }
    } else {
        for (int j = lane; j < NPT; j += 32) {
            float v = d[j];
            if (v < dist[KNN - 1]) {
                float cd = v; int ci = j;
#pragma unroll
                for (int p = 0; p < KNN; p++) {
                    if (cd < dist[p]) {
                        float td = dist[p]; int ti = ind[p];
                        dist[p] = cd; ind[p] = ci; cd = td; ci = ti;
                    }
                }
            }
        }
    }
#pragma unroll 1
    for (int r = 0; r < KNN; r++) {
        float cd = dist[0]; int ci = ind[0];
#pragma unroll
        for (int off = 16; off > 0; off >>= 1) {
            float od = __shfl_xor_sync(0xffffffffu, cd, off);
            int   oi = __shfl_xor_sync(0xffffffffu, ci, off);
            if (od < cd || (od == cd && oi < ci)) { cd = od; ci = oi; }
        }
        if (dist[0] == cd && ind[0] == ci) {
#pragma unroll
            for (int p = 0; p < KNN - 1; p++) { dist[p] = dist[p + 1]; ind[p] = ind[p + 1]; }
            dist[KNN - 1] = CUDART_INF_F; ind[KNN - 1] = 0x7fffffff;
        }
        if (lane == 0) outp[row * KNN + r] = ci;
    }
}

// ---------------- Wc = W[:, C:] - W[:, :C] ----------------
__global__ void k_wc(const float* __restrict__ W, int O, int C, float* __restrict__ Wc) {
    int i = blockIdx.x * 256 + threadIdx.x;
    if (i >= O * C) return;
    int o = i / C, c = i - o * C;
    Wc[i] = W[(size_t)o * 2 * C + C + c] - W[(size_t)o * 2 * C + c];
}

// ---------------- tiled NT GEMM, 128xBN, double-buffered smem, FFMA2 --------------------
template <int BN>
__global__ void __launch_bounds__(16 * (BN / 8))
k_gemm(const float* __restrict__ A, int rsA,
       const float* __restrict__ W, int rsW,
       int Kdim, int Odim,
       const float* __restrict__ scale, const float* __restrict__ bias,
       const float* __restrict__ extra,
       float* __restrict__ outp, int rsOut, int act) {
    constexpr int T  = 16 * (BN / 8);
    constexpr int AI = 256 / T;
    int m0 = blockIdx.x * 128;
    int o0 = blockIdx.y * BN;
    __shared__ float sA[2][16][132];
    __shared__ float sB[2][16][BN + 4];
    unsigned long long acc2[8][4];
#pragma unroll
    for (int i = 0; i < 8; i++)
#pragma unroll
        for (int j = 0; j < 4; j++) acc2[i][j] = 0ull;
    int t = threadIdx.x;
    int mi = t & 15, nj = t >> 4;

    float rA[AI][8], rB[8];
#pragma unroll
    for (int ia = 0; ia < AI; ia++) {
        int s = t + ia * T;
        int row = s >> 1, lka = (s & 1) * 8;
        const float* ar = A + (size_t)(m0 + row) * rsA + lka;
#pragma unroll
        for (int q = 0; q < 8; q++) rA[ia][q] = ar[q];
    }
    {
        int row = t >> 1, lkb = (t & 1) * 8;
        const float* wr = W + (size_t)(o0 + row) * rsW + lkb;
#pragma unroll
        for (int q = 0; q < 8; q++) rB[q] = wr[q];
    }
    int p = 0;
    for (int k0 = 0; k0 < Kdim; k0 += 16, p ^= 1) {
#pragma unroll
        for (int ia = 0; ia < AI; ia++) {
            int s = t + ia * T;
            int row = s >> 1, lka = (s & 1) * 8;
#pragma unroll
            for (int q = 0; q < 8; q++) sA[p][lka + q][row] = rA[ia][q];
        }
        {
            int row = t >> 1, lkb = (t & 1) * 8;
#pragma unroll
            for (int q = 0; q < 8; q++) sB[p][lkb + q][row] = rB[q];
        }
        __syncthreads();
        int kn = k0 + 16;
        if (kn < Kdim) {
#pragma unroll
            for (int ia = 0; ia < AI; ia++) {
                int s = t + ia * T;
                int row = s >> 1, lka = (s & 1) * 8;
                const float* ar = A + (size_t)(m0 + row) * rsA + kn + lka;
#pragma unroll
                for (int q = 0; q < 8; q++) rA[ia][q] = ar[q];
            }
            int row = t >> 1, lkb = (t & 1) * 8;
            const float* wr = W + (size_t)(o0 + row) * rsW + kn + lkb;
#pragma unroll
            for (int q = 0; q < 8; q++) rB[q] = wr[q];
        }
#pragma unroll
        for (int kk = 0; kk < 16; kk++) {
            float4 a0 = *(const float4*)&sA[p][kk][mi * 4];
            float4 a1 = *(const float4*)&sA[p][kk][64 + mi * 4];
            unsigned long long bp[4];
            bp[0] = *(const unsigned long long*)&sB[p][kk][nj * 4];
            bp[1] = *(const unsigned long long*)&sB[p][kk][nj * 4 + 2];
            bp[2] = *(const unsigned long long*)&sB[p][kk][BN / 2 + nj * 4];
            bp[3] = *(const unsigned long long*)&sB[p][kk][BN / 2 + nj * 4 + 2];
            float av[8] = {a0.x, a0.y, a0.z, a0.w, a1.x, a1.y, a1.z, a1.w};
#pragma unroll
            for (int i = 0; i < 8; i++) {
                unsigned long long ai = pk2(av[i]);
#pragma unroll
                for (int jp = 0; jp < 4; jp++) fma2(acc2[i][jp], ai, bp[jp]);
            }
        }
    }
    float accf[8][8];
#pragma unroll
    for (int i = 0; i < 8; i++)
#pragma unroll
        for (int jp = 0; jp < 4; jp++) {
            float2 f = upk2(acc2[i][jp]);
            accf[i][jp * 2] = f.x;
            accf[i][jp * 2 + 1] = f.y;
        }
#pragma unroll
    for (int ih = 0; ih < 2; ih++)
#pragma unroll
        for (int i = 0; i < 4; i++) {
            int m = m0 + ih * 64 + mi * 4 + i;
            int bat = m >> 12;
#pragma unroll
            for (int jh = 0; jh < 2; jh++) {
                int ob = o0 + jh * (BN / 2) + nj * 4;
                float4 v;
                float* vv = &v.x;
#pragma unroll
                for (int c = 0; c < 4; c++) {
                    int o = ob + c;
                    float x = accf[ih * 4 + i][jh * 4 + c];
                    if (act) {
                        if (extra) x += extra[bat * Odim + o];
                        x = x * scale[o] + bias[o];
                        x = x > 0.f ? x : 0.2f * x;
                    }
                    vv[c] = x;
                }
                *(float4*)(outp + (size_t)m * rsOut + ob) = v;
            }
        }
}

// ---------------- fused edge conv (layers 2-4), FFMA2 paired outputs -------------------
__global__ void k_edge(const float* __restrict__ Xin, int rsIn,
                       const int* __restrict__ idx,
                       const float* __restrict__ W, int rsW, int C, int Odim,
                       const float* __restrict__ base,
                       const float* __restrict__ scale, const float* __restrict__ bias,
                       float* __restrict__ outp, int rsOut) {
    int p0 = blockIdx.x * 4;
    int o0 = blockIdx.y * 64;
    int b  = p0 >> 12;
    __shared__ float sW[32][68];
    __shared__ float sN[32][85];
    __shared__ int   sIdx[80];
    __shared__ float sRed[4][64][4];
    int t = threadIdx.x;
    if (t < 80) sIdx[t] = idx[p0 * KNN + t];
    __syncthreads();
    unsigned long long acc2[2][5];
#pragma unroll
    for (int i = 0; i < 2; i++)
#pragma unroll
        for (int j = 0; j < 5; j++) acc2[i][j] = 0ull;
    int og = t & 15;
    int kpg = t >> 4;
    for (int c0 = 0; c0 < C; c0 += 32) {
        {
            int r = t >> 2;
            int cc0 = (t & 3) * 8;
            const float* wr = W + (size_t)(o0 + r) * rsW + c0 + cc0;
#pragma unroll
            for (int q = 0; q < 8; q++) sW[cc0 + q][r] = wr[q];
        }
        {
            int w = t >> 5, lane = t & 31;
#pragma unroll
            for (int rr = 0; rr < 10; rr++) {
                int kp = w * 10 + rr;
                int nb = sIdx[kp];
                sN[lane][kp] = Xin[((size_t)(b * NPT + nb)) * rsIn + c0 + lane];
            }
        }
        __syncthreads();
#pragma unroll 4
        for (int cc = 0; cc < 32; cc++) {
            unsigned long long wp0 = *(const unsigned long long*)&sW[cc][og * 4];
            unsigned long long wp1 = *(const unsigned long long*)&sW[cc][og * 4 + 2];
#pragma unroll
            for (int kk = 0; kk < 5; kk++) {
                unsigned long long nv2 = pk2(sN[cc][kpg * 5 + kk]);
                fma2(acc2[0][kk], wp0, nv2);
                fma2(acc2[1][kk], wp1, nv2);
            }
        }
        __syncthreads();
    }
    float acc[4][5];
#pragma unroll
    for (int pp = 0; pp < 2; pp++)
#pragma unroll
        for (int kk = 0; kk < 5; kk++) {
            float2 f = upk2(acc2[pp][kk]);
            acc[pp * 2][kk]     = f.x;
            acc[pp * 2 + 1][kk] = f.y;
        }
    int p = kpg >> 2, sub = kpg & 3;
#pragma unroll
    for (int oi = 0; oi < 4; oi++) {
        float m = acc[oi][0];
#pragma unroll
        for (int kk = 1; kk < 5; kk++) m = fmaxf(m, acc[oi][kk]);
        sRed[p][og * 4 + oi][sub] = m;
    }
    __syncthreads();
    int p2 = t >> 6, ol = t & 63;
    float m = fmaxf(fmaxf(sRed[p2][ol][0], sRed[p2][ol][1]),
                    fmaxf(sRed[p2][ol][2], sRed[p2][ol][3]));
    int o  = o0 + ol;
    int pt = p0 + p2;
    float v = scale[o] * (m + base[(size_t)pt * Odim + o]) + bias[o];
    v = v > 0.f ? v : 0.2f * v;
    outp[(size_t)pt * rsOut + o] = v;
}

// ---------------- edge conv layer 1 (C=3) ----------------
__global__ void k_edge1(const float* __restrict__ x, const int* __restrict__ idx,
                        const float* __restrict__ W1, const float* __restrict__ sc,
                        const float* __restrict__ bi, float* __restrict__ outp) {
    int pt = blockIdx.x;
    int b  = pt >> 12;
    int t  = threadIdx.x;
    __shared__ float snb[KNN][3];
    __shared__ float sx[3];
    if (t < KNN) {
        int nb = idx[pt * KNN + t];
        const float* src = x + (size_t)(b * NPT + nb) * 3;
        snb[t][0] = src[0]; snb[t][1] = src[1]; snb[t][2] = src[2];
    }
    if (t < 3) sx[t] = x[(size_t)pt * 3 + t];
    __syncthreads();
    float wd0 = W1[t * 6 + 0], wd1 = W1[t * 6 + 1], wd2 = W1[t * 6 + 2];
    float wc0 = W1[t * 6 + 3] - wd0, wc1 = W1[t * 6 + 4] - wd1, wc2 = W1[t * 6 + 5] - wd2;
    float m = -CUDART_INF_F;
#pragma unroll
    for (int k = 0; k < KNN; k++) {
        float v = wd0 * snb[k][0] + wd1 * snb[k][1] + wd2 * snb[k][2];
        m = fmaxf(m, v);
    }
    float v = sc[t] * (m + wc0 * sx[0] + wc1 * sx[1] + wc2 * sx[2]) + bi[t];
    v = v > 0.f ? v : 0.2f * v;
    outp[(size_t)pt * 512 + t] = v;
}

// ---------------- global max over N of g-activation ----------------
__global__ void k_rowmax(const float* __restrict__ actp, float* __restrict__ g) {
    int o = blockIdx.x * 256 + threadIdx.x;
    int b = blockIdx.y;
    const float* p = actp + (size_t)b * NPT * 1024 + o;
    float m0 = -CUDART_INF_F, m1 = m0, m2 = m0, m3 = m0;
    for (int n = 0; n < NPT; n += 4) {
        m0 = fmaxf(m0, p[(size_t)(n + 0) * 1024]);
        m1 = fmaxf(m1, p[(size_t)(n + 1) * 1024]);
        m2 = fmaxf(m2, p[(size_t)(n + 2) * 1024]);
        m3 = fmaxf(m3, p[(size_t)(n + 3) * 1024]);
    }
    g[b * 1024 + o] = fmaxf(fmaxf(m0, m1), fmaxf(m2, m3));
}

// ---------------- sterm[b][o] = Ws1[o, 512:1536] . g[b] ----------------
__global__ void k_sterm(const float* __restrict__ Ws1, const float* __restrict__ g,
                        float* __restrict__ st) {
    int i = blockIdx.x * 256 + threadIdx.x;
    if (i >= BATCH * 512) return;
    int b = i >> 9, o = i & 511;
    const float* w  = Ws1 + (size_t)o * 1536 + 512;
    const float* gb = g + b * 1024;
    float s = 0.f;
    for (int e = 0; e < 1024; e++) s = fmaf(w[e], gb[e], s);
    st[i] = s;
}

// ---------------- final classifier (O=13) ----------------
__global__ void k_out(const float* __restrict__ h2, const float* __restrict__ W3,
                      const float* __restrict__ b3, float* __restrict__ outp) {
    __shared__ float sW[13 * 256];
    __shared__ float sb[13];
    int t = threadIdx.x;
    for (int i = t; i < 13 * 256; i += 256) sW[i] = W3[i];
    if (t < 13) sb[t] = b3[t];
    __syncthreads();
    int m = blockIdx.x * 256 + t;
    float acc[13];
#pragma unroll
    for (int c = 0; c < 13; c++) acc[c] = 0.f;
    const float* h = h2 + (size_t)m * 256;
    for (int k = 0; k < 256; k++) {
        float xv = h[k];
#pragma unroll
        for (int c = 0; c < 13; c++) acc[c] = fmaf(xv, sW[c * 256 + k], acc[c]);
    }
#pragma unroll
    for (int c = 0; c < 13; c++) outp[(size_t)m * 13 + c] = acc[c] + sb[c];
}

// ---------------- host ----------------
static void edge_layer(float* xcat, int inOff, int C,
                       const float* W, const float* s, const float* b,
                       int O, int outOff,
                       float* xxp, float* distp, int* idxp, float* wcp, float* basep) {
    k_sqnorm<<<NB / 64, 64>>>(xcat + inOff, 512, C, xxp);
    k_dist<<<dim3(NPT / 128, NPT / 128, BATCH), 256>>>(xcat + inOff, 512, C, xxp, distp);
    k_topk<<<NB / 8, 256>>>(distp, idxp);
    k_wc<<<(O * C + 255) / 256, 256>>>(W, O, C, wcp);
    if (O % 128 == 0)
        k_gemm<128><<<dim3(NB / 128, O / 128), 256>>>(xcat + inOff, 512, wcp, C, C, O,
                                                      nullptr, nullptr, nullptr, basep, O, 0);
    else
        k_gemm<64><<<dim3(NB / 128, O / 64), 128>>>(xcat + inOff, 512, wcp, C, C, O,
                                                    nullptr, nullptr, nullptr, basep, O, 0);
    k_edge<<<dim3(NB / 4, O / 64), 256>>>(xcat + inOff, 512, idxp, W, 2 * C, C, O,
                                          basep, s, b, xcat + outOff, 512);
}

extern "C" void kernel_launch(void* const* d_in, const int* in_sizes, int n_in,
                              void* d_out, int out_size) {
    const float* x   = (const float*)d_in[0];
    const float* W1  = (const float*)d_in[1];
    const float* s1  = (const float*)d_in[2];
    const float* b1  = (const float*)d_in[3];
    const float* W2  = (const float*)d_in[4];
    const float* s2  = (const float*)d_in[5];
    const float* b2  = (const float*)d_in[6];
    const float* W3  = (const float*)d_in[7];
    const float* s3  = (const float*)d_in[8];
    const float* b3  = (const float*)d_in[9];
    const float* W4  = (const float*)d_in[10];
    const float* s4  = (const float*)d_in[11];
    const float* b4  = (const float*)d_in[12];
    const float* Wg  = (const float*)d_in[13];
    const float* sg  = (const float*)d_in[14];
    const float* bg  = (const float*)d_in[15];
    const float* Ws1 = (const float*)d_in[16];
    const float* ss1 = (const float*)d_in[17];
    const float* bs1 = (const float*)d_in[18];
    const float* Ws2 = (const float*)d_in[19];
    const float* ss2 = (const float*)d_in[20];
    const float* bs2 = (const float*)d_in[21];
    const float* Ws3 = (const float*)d_in[22];
    const float* bs3 = (const float*)d_in[23];
    float* outp = (float*)d_out;

    float *dist, *xx, *xcat, *base, *wc, *act, *gvec, *sterm, *h1, *h2;
    int* idxp;
    cudaGetSymbolAddress((void**)&dist,  g_dist);
    cudaGetSymbolAddress((void**)&idxp,  g_idx);
    cudaGetSymbolAddress((void**)&xx,    g_xx);
    cudaGetSymbolAddress((void**)&xcat,  g_xcat);
    cudaGetSymbolAddress((void**)&base,  g_base);
    cudaGetSymbolAddress((void**)&wc,    g_Wc);
    cudaGetSymbolAddress((void**)&act,   g_act);
    cudaGetSymbolAddress((void**)&gvec,  g_gvec);
    cudaGetSymbolAddress((void**)&sterm, g_sterm);
    cudaGetSymbolAddress((void**)&h1,    g_h1);
    cudaGetSymbolAddress((void**)&h2,    g_h2);

    // Layer 1 (kNN on raw xyz, C=3, O=64 -> xcat[:, 0:64])
    k_sqnorm<<<NB / 64, 64>>>(x, 3, 3, xx);
    k_dist<<<dim3(NPT / 128, NPT / 128, BATCH), 256>>>(x, 3, 3, xx, dist);
    k_topk<<<NB / 8, 256>>>(dist, idxp);
    k_edge1<<<NB, 64>>>(x, idxp, W1, s1, b1, xcat);

    // Layers 2-4
    edge_layer(xcat, 0,   64,  W2, s2, b2, 64,  64,  xx, dist, idxp, wc, base);
    edge_layer(xcat, 64,  64,  W3, s3, b3, 128, 128, xx, dist, idxp, wc, base);
    edge_layer(xcat, 128, 128, W4, s4, b4, 256, 256, xx, dist, idxp, wc, base);

    // Global feature: g = max_n lrelu(sg*(xcat.Wg^T)+bg)
    k_gemm<128><<<dim3(NB / 128, 1024 / 128), 256>>>(xcat, 512, Wg, 512, 512, 1024,
                                                     sg, bg, nullptr, act, 1024, 1);
    k_rowmax<<<dim3(4, BATCH), 256>>>(act, gvec);

    // Ws1: split [xcat ; g] -> GEMM on xcat + per-batch sterm from g
    k_sterm<<<4, 256>>>(Ws1, gvec, sterm);
    k_gemm<128><<<dim3(NB / 128, 512 / 128), 256>>>(xcat, 512, Ws1, 1536, 512, 512,
                                                    ss1, bs1, sterm, h1, 512, 1);
    // Ws2
    k_gemm<128><<<dim3(NB / 128, 256 / 128), 256>>>(h1, 512, Ws2, 512, 512, 256,
                                                    ss2, bs2, nullptr, h2, 256, 1);
    // Ws3 (13 classes) + bias
    k_out<<<NB / 256, 256>>>(h2, Ws3, bs3, outp);
}

// round 17
// speedup vs baseline: 1.0997x; 1.0997x over previous
#include <cuda_runtime.h>
#include <math_constants.h>
#include <cstdint>
#include <cstddef>

#define BATCH 2
#define NPT   4096
#define NB    (BATCH * NPT)
#define KNN   20
#define TCAP  512

// ---------------- scratch (device globals; no allocation) ----------------
__device__ float g_dist[(size_t)NB * NPT];     // 134 MB distance matrix (reused per layer)
__device__ int   g_idx[NB * KNN];
__device__ float g_xx[NB];
__device__ float g_xcat[(size_t)NB * 512];     // x1|x2|x3|x4 at channel offsets 0/64/128/256
__device__ float g_base[(size_t)NB * 256];
__device__ float g_Wc[256 * 128];
__device__ float g_act[(size_t)NB * 1024];
__device__ float g_part[BATCH * 32 * 1024];    // rowmax partials
__device__ float g_gvec[BATCH * 1024];
__device__ float g_sterm[BATCH * 512];
__device__ float g_h1[(size_t)NB * 512];
__device__ float g_h2[(size_t)NB * 256];

// ---------------- packed f32x2 helpers (sm_103a FFMA2) ----------------
__device__ __forceinline__ unsigned long long pk2(float x) {
    unsigned long long r;
    asm("mov.b64 %0, {%1, %1};" : "=l"(r) : "f"(x));
    return r;
}
__device__ __forceinline__ void fma2(unsigned long long& c, unsigned long long a,
                                     unsigned long long b) {
    asm("fma.rn.f32x2 %0, %1, %2, %0;" : "+l"(c) : "l"(a), "l"(b));
}
__device__ __forceinline__ float2 upk2(unsigned long long v) {
    float2 r;
    asm("mov.b64 {%0, %1}, %2;" : "=f"(r.x), "=f"(r.y) : "l"(v));
    return r;
}

// ---------------- squared norms ----------------
__global__ void k_sqnorm(const float* __restrict__ X, int rs, int C, float* __restrict__ xx) {
    int i = blockIdx.x * blockDim.x + threadIdx.x;
    if (i >= NB) return;
    const float* r = X + (size_t)i * rs;
    float s = 0.f;
    for (int c = 0; c < C; c++) s = fmaf(r[c], r[c], s);
    xx[i] = s;
}

// ---------------- pairwise distance: symmetric tiles, double-buffered smem, FFMA2 ------
// grid (NPT/128, NPT/128, B), block 256; FMA chain bit-identical to round-13.
__global__ void __launch_bounds__(256)
k_dist(const float* __restrict__ X, int rs, int C,
       const float* __restrict__ xx, float* __restrict__ D) {
    if (blockIdx.y < blockIdx.x) return;   // lower triangle via mirror
    int m0 = blockIdx.x * 128;
    int n0 = blockIdx.y * 128;
    int b  = blockIdx.z;
    const float* Xb  = X  + (size_t)b * NPT * rs;
    const float* xxb = xx + b * NPT;
    __shared__ float sA[2][16][132];
    __shared__ float sB[2][16][132];
    unsigned long long acc2[8][4];
#pragma unroll
    for (int i = 0; i < 8; i++)
#pragma unroll
        for (int j = 0; j < 4; j++) acc2[i][j] = 0ull;
    int t = threadIdx.x;
    int mi = t & 15, nj = t >> 4;
    int lrow = t >> 1, lk = (t & 1) * 8;
    const float* arow = Xb + (size_t)(m0 + lrow) * rs + lk;
    const float* brow = Xb + (size_t)(n0 + lrow) * rs + lk;

    float rA[8], rB[8];
#pragma unroll
    for (int q = 0; q < 8; q++) {            // prologue: chunk k0=0
        bool ok = (lk + q) < C;
        rA[q] = ok ? arow[q] : 0.f;
        rB[q] = ok ? brow[q] : 0.f;
    }
    int p = 0;
    for (int k0 = 0; k0 < C; k0 += 16, p ^= 1) {
#pragma unroll
        for (int q = 0; q < 8; q++) {
            sA[p][lk + q][lrow] = rA[q];
            sB[p][lk + q][lrow] = rB[q];
        }
        __syncthreads();
        int kn = k0 + 16;
        if (kn < C) {                        // prefetch next chunk during compute
#pragma unroll
            for (int q = 0; q < 8; q++) {
                bool ok = (kn + lk + q) < C;
                rA[q] = ok ? arow[kn + q] : 0.f;
                rB[q] = ok ? brow[kn + q] : 0.f;
            }
        }
#pragma unroll
        for (int kk = 0; kk < 16; kk++) {
            float4 a0 = *(const float4*)&sA[p][kk][mi * 4];
            float4 a1 = *(const float4*)&sA[p][kk][64 + mi * 4];
            unsigned long long bp[4];
            bp[0] = *(const unsigned long long*)&sB[p][kk][nj * 4];
            bp[1] = *(const unsigned long long*)&sB[p][kk][nj * 4 + 2];
            bp[2] = *(const unsigned long long*)&sB[p][kk][64 + nj * 4];
            bp[3] = *(const unsigned long long*)&sB[p][kk][64 + nj * 4 + 2];
            float av[8] = {a0.x, a0.y, a0.z, a0.w, a1.x, a1.y, a1.z, a1.w};
#pragma unroll
            for (int i = 0; i < 8; i++) {
                unsigned long long ai = pk2(av[i]);
#pragma unroll
                for (int jp = 0; jp < 4; jp++) fma2(acc2[i][jp], ai, bp[jp]);
            }
        }
    }
    float accf[8][8];
#pragma unroll
    for (int i = 0; i < 8; i++)
#pragma unroll
        for (int jp = 0; jp < 4; jp++) {
            float2 f = upk2(acc2[i][jp]);
            accf[i][jp * 2] = f.x;
            accf[i][jp * 2 + 1] = f.y;
        }
    // normal tile store
#pragma unroll
    for (int ih = 0; ih < 2; ih++)
#pragma unroll
        for (int i = 0; i < 4; i++) {
            int ig = m0 + ih * 64 + mi * 4 + i;
            float xi = xxb[ig];
            float* dst = D + ((size_t)b * NPT + ig) * NPT;
#pragma unroll
            for (int jh = 0; jh < 2; jh++) {
                int j0 = n0 + jh * 64 + nj * 4;
                float4 xj = *(const float4*)&xxb[j0];
                float4 v;
                v.x = xi + xj.x - 2.f * accf[ih * 4 + i][jh * 4 + 0];
                v.y = xi + xj.y - 2.f * accf[ih * 4 + i][jh * 4 + 1];
                v.z = xi + xj.z - 2.f * accf[ih * 4 + i][jh * 4 + 2];
                v.w = xi + xj.w - 2.f * accf[ih * 4 + i][jh * 4 + 3];
                *(float4*)(dst + j0) = v;
            }
        }
    // mirrored tile store (off-diagonal blocks only); bitwise-identical by commutativity
    if (blockIdx.y > blockIdx.x) {
#pragma unroll
        for (int jh = 0; jh < 2; jh++)
#pragma unroll
            for (int c = 0; c < 4; c++) {
                int jg = n0 + jh * 64 + nj * 4 + c;
                float xj = xxb[jg];
                float* dst = D + ((size_t)b * NPT + jg) * NPT;
#pragma unroll
                for (int ih = 0; ih < 2; ih++) {
                    int i0 = m0 + ih * 64 + mi * 4;
                    float4 xi4 = *(const float4*)&xxb[i0];
                    float4 v;
                    v.x = xj + xi4.x - 2.f * accf[ih * 4 + 0][jh * 4 + c];
                    v.y = xj + xi4.y - 2.f * accf[ih * 4 + 1][jh * 4 + c];
                    v.z = xj + xi4.z - 2.f * accf[ih * 4 + 2][jh * 4 + c];
                    v.w = xj + xi4.w - 2.f * accf[ih * 4 + 3][jh * 4 + c];
                    *(float4*)(dst + i0) = v;
                }
            }
    }
}

// ---------------- threshold-filtered exact top-20 smallest (stable ties) ----------------
__global__ void k_topk(const float* __restrict__ D, int* __restrict__ outp) {
    __shared__ float sVal[8][TCAP];
    __shared__ int   sInd[8][TCAP];
    int w    = threadIdx.x >> 5;
    int row  = blockIdx.x * 8 + w;
    int lane = threadIdx.x & 31;
    const float* d = D + (size_t)row * NPT;

    // ---- pass 1: threshold = 20th smallest of first 256 (float4 sample) ----
    float sd[8];
#pragma unroll
    for (int p = 0; p < 8; p++) sd[p] = CUDART_INF_F;
#pragma unroll
    for (int q = 0; q < 2; q++) {
        float4 v4 = *(const float4*)(d + lane * 4 + q * 128);
        float vv[4] = {v4.x, v4.y, v4.z, v4.w};
#pragma unroll
        for (int e = 0; e < 4; e++) {
            float cd = vv[e];
#pragma unroll
            for (int p = 0; p < 8; p++) {
                if (cd < sd[p]) { float tm = sd[p]; sd[p] = cd; cd = tm; }
            }
        }
    }
    float t = CUDART_INF_F;
#pragma unroll 1
    for (int r = 0; r < KNN; r++) {
        float cd = sd[0]; int cl = lane;
#pragma unroll
        for (int off = 16; off > 0; off >>= 1) {
            float od = __shfl_xor_sync(0xffffffffu, cd, off);
            int   ol = __shfl_xor_sync(0xffffffffu, cl, off);
            if (od < cd || (od == cd && ol < cl)) { cd = od; cl = ol; }
        }
        if (lane == cl) {
#pragma unroll
            for (int p = 0; p < 7; p++) sd[p] = sd[p + 1];
            sd[7] = CUDART_INF_F;
        }
        t = cd;
    }

    // ---- pass 2: float4 scan, compact v<=t in ascending-j order ----
    int cnt = 0;
#pragma unroll 1
    for (int j0 = lane * 4; j0 < NPT; j0 += 128) {
        float4 v4 = *(const float4*)(d + j0);
        float vv[4] = {v4.x, v4.y, v4.z, v4.w};
        bool pr[4];
        int nl = 0;
#pragma unroll
        for (int e = 0; e < 4; e++) { pr[e] = (vv[e] <= t); nl += pr[e]; }
        int sc = nl;
#pragma unroll
        for (int off = 1; off < 32; off <<= 1) {
            int o = __shfl_up_sync(0xffffffffu, sc, off);
            if (lane >= off) sc += o;
        }
        int total = __shfl_sync(0xffffffffu, sc, 31);
        int pos = cnt + sc - nl;   // exclusive prefix: ascending (lane, e) = ascending j
#pragma unroll
        for (int e = 0; e < 4; e++) {
            if (pr[e]) {
                if (pos < TCAP) { sVal[w][pos] = vv[e]; sInd[w][pos] = j0 + e; }
                pos++;
            }
        }
        cnt += total;
    }

    // ---- pass 3: exact stable top-20 ----
    float dist[KNN]; int ind[KNN];
#pragma unroll
    for (int p = 0; p < KNN; p++) { dist[p] = CUDART_INF_F; ind[p] = 0x7fffffff; }
    if (cnt <= TCAP) {
        for (int i = lane; i < cnt; i += 32) {
            float v = sVal[w][i];
            if (v < dist[KNN - 1]) {
                float cd = v; int ci = sInd[w][i];
#pragma unroll
                for (int p = 0; p < KNN; p++) {
                    if (cd < dist[p]) {
                        float td = dist[p]; int ti = ind[p];
                        dist[p] = cd; ind[p] = ci; cd = td; ci = ti;
                    }
                }
            }
        }
    } else {
        for (int j = lane; j < NPT; j += 32) {
            float v = d[j];
            if (v < dist[KNN - 1]) {
                float cd = v; int ci = j;
#pragma unroll
                for (int p = 0; p < KNN; p++) {
                    if (cd < dist[p]) {
                        float td = dist[p]; int ti = ind[p];
                        dist[p] = cd; ind[p] = ci; cd = td; ci = ti;
                    }
                }
            }
        }
    }
#pragma unroll 1
    for (int r = 0; r < KNN; r++) {
        float cd = dist[0]; int ci = ind[0];
#pragma unroll
        for (int off = 16; off > 0; off >>= 1) {
            float od = __shfl_xor_sync(0xffffffffu, cd, off);
            int   oi = __shfl_xor_sync(0xffffffffu, ci, off);
            if (od < cd || (od == cd && oi < ci)) { cd = od; ci = oi; }
        }
        if (dist[0] == cd && ind[0] == ci) {
#pragma unroll
            for (int p = 0; p < KNN - 1; p++) { dist[p] = dist[p + 1]; ind[p] = ind[p + 1]; }
            dist[KNN - 1] = CUDART_INF_F; ind[KNN - 1] = 0x7fffffff;
        }
        if (lane == 0) outp[row * KNN + r] = ci;
    }
}

// ---------------- Wc = W[:, C:] - W[:, :C] ----------------
__global__ void k_wc(const float* __restrict__ W, int O, int C, float* __restrict__ Wc) {
    int i = blockIdx.x * 256 + threadIdx.x;
    if (i >= O * C) return;
    int o = i / C, c = i - o * C;
    Wc[i] = W[(size_t)o * 2 * C + C + c] - W[(size_t)o * 2 * C + c];
}

// ---------------- tiled NT GEMM, 128xBN, double-buffered smem, FFMA2 --------------------
template <int BN>
__global__ void __launch_bounds__(16 * (BN / 8))
k_gemm(const float* __restrict__ A, int rsA,
       const float* __restrict__ W, int rsW,
       int Kdim, int Odim,
       const float* __restrict__ scale, const float* __restrict__ bias,
       const float* __restrict__ extra,
       float* __restrict__ outp, int rsOut, int act) {
    constexpr int T  = 16 * (BN / 8);
    constexpr int AI = 256 / T;
    int m0 = blockIdx.x * 128;
    int o0 = blockIdx.y * BN;
    __shared__ float sA[2][16][132];
    __shared__ float sB[2][16][BN + 4];
    unsigned long long acc2[8][4];
#pragma unroll
    for (int i = 0; i < 8; i++)
#pragma unroll
        for (int j = 0; j < 4; j++) acc2[i][j] = 0ull;
    int t = threadIdx.x;
    int mi = t & 15, nj = t >> 4;

    float rA[AI][8], rB[8];
#pragma unroll
    for (int ia = 0; ia < AI; ia++) {
        int s = t + ia * T;
        int row = s >> 1, lka = (s & 1) * 8;
        const float* ar = A + (size_t)(m0 + row) * rsA + lka;
#pragma unroll
        for (int q = 0; q < 8; q++) rA[ia][q] = ar[q];
    }
    {
        int row = t >> 1, lkb = (t & 1) * 8;
        const float* wr = W + (size_t)(o0 + row) * rsW + lkb;
#pragma unroll
        for (int q = 0; q < 8; q++) rB[q] = wr[q];
    }
    int p = 0;
    for (int k0 = 0; k0 < Kdim; k0 += 16, p ^= 1) {
#pragma unroll
        for (int ia = 0; ia < AI; ia++) {
            int s = t + ia * T;
            int row = s >> 1, lka = (s & 1) * 8;
#pragma unroll
            for (int q = 0; q < 8; q++) sA[p][lka + q][row] = rA[ia][q];
        }
        {
            int row = t >> 1, lkb = (t & 1) * 8;
#pragma unroll
            for (int q = 0; q < 8; q++) sB[p][lkb + q][row] = rB[q];
        }
        __syncthreads();
        int kn = k0 + 16;
        if (kn < Kdim) {
#pragma unroll
            for (int ia = 0; ia < AI; ia++) {
                int s = t + ia * T;
                int row = s >> 1, lka = (s & 1) * 8;
                const float* ar = A + (size_t)(m0 + row) * rsA + kn + lka;
#pragma unroll
                for (int q = 0; q < 8; q++) rA[ia][q] = ar[q];
            }
            int row = t >> 1, lkb = (t & 1) * 8;
            const float* wr = W + (size_t)(o0 + row) * rsW + kn + lkb;
#pragma unroll
            for (int q = 0; q < 8; q++) rB[q] = wr[q];
        }
#pragma unroll
        for (int kk = 0; kk < 16; kk++) {
            float4 a0 = *(const float4*)&sA[p][kk][mi * 4];
            float4 a1 = *(const float4*)&sA[p][kk][64 + mi * 4];
            unsigned long long bp[4];
            bp[0] = *(const unsigned long long*)&sB[p][kk][nj * 4];
            bp[1] = *(const unsigned long long*)&sB[p][kk][nj * 4 + 2];
            bp[2] = *(const unsigned long long*)&sB[p][kk][BN / 2 + nj * 4];
            bp[3] = *(const unsigned long long*)&sB[p][kk][BN / 2 + nj * 4 + 2];
            float av[8] = {a0.x, a0.y, a0.z, a0.w, a1.x, a1.y, a1.z, a1.w};
#pragma unroll
            for (int i = 0; i < 8; i++) {
                unsigned long long ai = pk2(av[i]);
#pragma unroll
                for (int jp = 0; jp < 4; jp++) fma2(acc2[i][jp], ai, bp[jp]);
            }
        }
    }
    float accf[8][8];
#pragma unroll
    for (int i = 0; i < 8; i++)
#pragma unroll
        for (int jp = 0; jp < 4; jp++) {
            float2 f = upk2(acc2[i][jp]);
            accf[i][jp * 2] = f.x;
            accf[i][jp * 2 + 1] = f.y;
        }
#pragma unroll
    for (int ih = 0; ih < 2; ih++)
#pragma unroll
        for (int i = 0; i < 4; i++) {
            int m = m0 + ih * 64 + mi * 4 + i;
            int bat = m >> 12;
#pragma unroll
            for (int jh = 0; jh < 2; jh++) {
                int ob = o0 + jh * (BN / 2) + nj * 4;
                float4 v;
                float* vv = &v.x;
#pragma unroll
                for (int c = 0; c < 4; c++) {
                    int o = ob + c;
                    float x = accf[ih * 4 + i][jh * 4 + c];
                    if (act) {
                        if (extra) x += extra[bat * Odim + o];
                        x = x * scale[o] + bias[o];
                        x = x > 0.f ? x : 0.2f * x;
                    }
                    vv[c] = x;
                }
                *(float4*)(outp + (size_t)m * rsOut + ob) = v;
            }
        }
}

// ---------------- fused edge conv (layers 2-4), FFMA2 paired outputs -------------------
__global__ void k_edge(const float* __restrict__ Xin, int rsIn,
                       const int* __restrict__ idx,
                       const float* __restrict__ W, int rsW, int C, int Odim,
                       const float* __restrict__ base,
                       const float* __restrict__ scale, const float* __restrict__ bias,
                       float* __restrict__ outp, int rsOut) {
    int p0 = blockIdx.x * 4;
    int o0 = blockIdx.y * 64;
    int b  = p0 >> 12;
    __shared__ float sW[32][68];
    __shared__ float sN[32][85];
    __shared__ int   sIdx[80];
    __shared__ float sRed[4][64][4];
    int t = threadIdx.x;
    if (t < 80) sIdx[t] = idx[p0 * KNN + t];
    __syncthreads();
    unsigned long long acc2[2][5];
#pragma unroll
    for (int i = 0; i < 2; i++)
#pragma unroll
        for (int j = 0; j < 5; j++) acc2[i][j] = 0ull;
    int og = t & 15;
    int kpg = t >> 4;
    for (int c0 = 0; c0 < C; c0 += 32) {
        {
            int r = t >> 2;
            int cc0 = (t & 3) * 8;
            const float* wr = W + (size_t)(o0 + r) * rsW + c0 + cc0;
#pragma unroll
            for (int q = 0; q < 8; q++) sW[cc0 + q][r] = wr[q];
        }
        {
            int w = t >> 5, lane = t & 31;
#pragma unroll
            for (int rr = 0; rr < 10; rr++) {
                int kp = w * 10 + rr;
                int nb = sIdx[kp];
                sN[lane][kp] = Xin[((size_t)(b * NPT + nb)) * rsIn + c0 + lane];
            }
        }
        __syncthreads();
#pragma unroll 4
        for (int cc = 0; cc < 32; cc++) {
            unsigned long long wp0 = *(const unsigned long long*)&sW[cc][og * 4];
            unsigned long long wp1 = *(const unsigned long long*)&sW[cc][og * 4 + 2];
#pragma unroll
            for (int kk = 0; kk < 5; kk++) {
                unsigned long long nv2 = pk2(sN[cc][kpg * 5 + kk]);
                fma2(acc2[0][kk], wp0, nv2);
                fma2(acc2[1][kk], wp1, nv2);
            }
        }
        __syncthreads();
    }
    float acc[4][5];
#pragma unroll
    for (int pp = 0; pp < 2; pp++)
#pragma unroll
        for (int kk = 0; kk < 5; kk++) {
            float2 f = upk2(acc2[pp][kk]);
            acc[pp * 2][kk]     = f.x;
            acc[pp * 2 + 1][kk] = f.y;
        }
    int p = kpg >> 2, sub = kpg & 3;
#pragma unroll
    for (int oi = 0; oi < 4; oi++) {
        float m = acc[oi][0];
#pragma unroll
        for (int kk = 1; kk < 5; kk++) m = fmaxf(m, acc[oi][kk]);
        sRed[p][og * 4 + oi][sub] = m;
    }
    __syncthreads();
    int p2 = t >> 6, ol = t & 63;
    float m = fmaxf(fmaxf(sRed[p2][ol][0], sRed[p2][ol][1]),
                    fmaxf(sRed[p2][ol][2], sRed[p2][ol][3]));
    int o  = o0 + ol;
    int pt = p0 + p2;
    float v = scale[o] * (m + base[(size_t)pt * Odim + o]) + bias[o];
    v = v > 0.f ? v : 0.2f * v;
    outp[(size_t)pt * rsOut + o] = v;
}

// ---------------- edge conv layer 1 (C=3) ----------------
__global__ void k_edge1(const float* __restrict__ x, const int* __restrict__ idx,
                        const float* __restrict__ W1, const float* __restrict__ sc,
                        const float* __restrict__ bi, float* __restrict__ outp) {
    int pt = blockIdx.x;
    int b  = pt >> 12;
    int t  = threadIdx.x;
    __shared__ float snb[KNN][3];
    __shared__ float sx[3];
    if (t < KNN) {
        int nb = idx[pt * KNN + t];
        const float* src = x + (size_t)(b * NPT + nb) * 3;
        snb[t][0] = src[0]; snb[t][1] = src[1]; snb[t][2] = src[2];
    }
    if (t < 3) sx[t] = x[(size_t)pt * 3 + t];
    __syncthreads();
    float wd0 = W1[t * 6 + 0], wd1 = W1[t * 6 + 1], wd2 = W1[t * 6 + 2];
    float wc0 = W1[t * 6 + 3] - wd0, wc1 = W1[t * 6 + 4] - wd1, wc2 = W1[t * 6 + 5] - wd2;
    float m = -CUDART_INF_F;
#pragma unroll
    for (int k = 0; k < KNN; k++) {
        float v = wd0 * snb[k][0] + wd1 * snb[k][1] + wd2 * snb[k][2];
        m = fmaxf(m, v);
    }
    float v = sc[t] * (m + wc0 * sx[0] + wc1 * sx[1] + wc2 * sx[2]) + bi[t];
    v = v > 0.f ? v : 0.2f * v;
    outp[(size_t)pt * 512 + t] = v;
}

// ---------------- global max over N: phase 1 (partials over 128-row chunks) ------------
// grid (4, 32, BATCH), block 256; exact (fmax associative+commutative, finite inputs)
__global__ void k_rowmax1(const float* __restrict__ actp, float* __restrict__ part) {
    int o  = blockIdx.x * 256 + threadIdx.x;
    int nc = blockIdx.y;
    int b  = blockIdx.z;
    const float* p = actp + ((size_t)b * NPT + nc * 128) * 1024 + o;
    float m0 = -CUDART_INF_F, m1 = m0, m2 = m0, m3 = m0;
#pragma unroll 4
    for (int n = 0; n < 128; n += 4) {
        m0 = fmaxf(m0, p[(size_t)(n + 0) * 1024]);
        m1 = fmaxf(m1, p[(size_t)(n + 1) * 1024]);
        m2 = fmaxf(m2, p[(size_t)(n + 2) * 1024]);
        m3 = fmaxf(m3, p[(size_t)(n + 3) * 1024]);
    }
    part[((size_t)b * 32 + nc) * 1024 + o] = fmaxf(fmaxf(m0, m1), fmaxf(m2, m3));
}

// ---------------- global max over N: phase 2 (reduce 32 partials) ----------------------
__global__ void k_rowmax2(const float* __restrict__ part, float* __restrict__ g) {
    int i = blockIdx.x * 256 + threadIdx.x;
    if (i >= BATCH * 1024) return;
    int b = i >> 10, o = i & 1023;
    float m = -CUDART_INF_F;
#pragma unroll
    for (int c = 0; c < 32; c++) m = fmaxf(m, part[((size_t)b * 32 + c) * 1024 + o]);
    g[i] = m;
}

// ---------------- sterm[b][o] = Ws1[o, 512:1536] . g[b] (warp-per-output, coalesced) ---
__global__ void k_sterm(const float* __restrict__ Ws1, const float* __restrict__ g,
                        float* __restrict__ st) {
    int gw   = (blockIdx.x * blockDim.x + threadIdx.x) >> 5;
    int lane = threadIdx.x & 31;
    if (gw >= BATCH * 512) return;
    int b = gw >> 9, o = gw & 511;
    const float* w  = Ws1 + (size_t)o * 1536 + 512;
    const float* gb = g + b * 1024;
    float s = 0.f;
#pragma unroll 8
    for (int e = lane; e < 1024; e += 32) s = fmaf(w[e], gb[e], s);
#pragma unroll
    for (int off = 16; off > 0; off >>= 1) s += __shfl_xor_sync(0xffffffffu, s, off);
    if (lane == 0) st[gw] = s;
}

// ---------------- final classifier (O=13) ----------------
__global__ void k_out(const float* __restrict__ h2, const float* __restrict__ W3,
                      const float* __restrict__ b3, float* __restrict__ outp) {
    __shared__ float sW[13 * 256];
    __shared__ float sb[13];
    int t = threadIdx.x;
    for (int i = t; i < 13 * 256; i += 256) sW[i] = W3[i];
    if (t < 13) sb[t] = b3[t];
    __syncthreads();
    int m = blockIdx.x * 256 + t;
    float acc[13];
#pragma unroll
    for (int c = 0; c < 13; c++) acc[c] = 0.f;
    const float* h = h2 + (size_t)m * 256;
    for (int k = 0; k < 256; k++) {
        float xv = h[k];
#pragma unroll
        for (int c = 0; c < 13; c++) acc[c] = fmaf(xv, sW[c * 256 + k], acc[c]);
    }
#pragma unroll
    for (int c = 0; c < 13; c++) outp[(size_t)m * 13 + c] = acc[c] + sb[c];
}

// ---------------- host ----------------
static void edge_layer(float* xcat, int inOff, int C,
                       const float* W, const float* s, const float* b,
                       int O, int outOff,
                       float* xxp, float* distp, int* idxp, float* wcp, float* basep) {
    k_sqnorm<<<NB / 64, 64>>>(xcat + inOff, 512, C, xxp);
    k_dist<<<dim3(NPT / 128, NPT / 128, BATCH), 256>>>(xcat + inOff, 512, C, xxp, distp);
    k_topk<<<NB / 8, 256>>>(distp, idxp);
    k_wc<<<(O * C + 255) / 256, 256>>>(W, O, C, wcp);
    if (O % 128 == 0)
        k_gemm<128><<<dim3(NB / 128, O / 128), 256>>>(xcat + inOff, 512, wcp, C, C, O,
                                                      nullptr, nullptr, nullptr, basep, O, 0);
    else
        k_gemm<64><<<dim3(NB / 128, O / 64), 128>>>(xcat + inOff, 512, wcp, C, C, O,
                                                    nullptr, nullptr, nullptr, basep, O, 0);
    k_edge<<<dim3(NB / 4, O / 64), 256>>>(xcat + inOff, 512, idxp, W, 2 * C, C, O,
                                          basep, s, b, xcat + outOff, 512);
}

extern "C" void kernel_launch(void* const* d_in, const int* in_sizes, int n_in,
                              void* d_out, int out_size) {
    const float* x   = (const float*)d_in[0];
    const float* W1  = (const float*)d_in[1];
    const float* s1  = (const float*)d_in[2];
    const float* b1  = (const float*)d_in[3];
    const float* W2  = (const float*)d_in[4];
    const float* s2  = (const float*)d_in[5];
    const float* b2  = (const float*)d_in[6];
    const float* W3  = (const float*)d_in[7];
    const float* s3  = (const float*)d_in[8];
    const float* b3  = (const float*)d_in[9];
    const float* W4  = (const float*)d_in[10];
    const float* s4  = (const float*)d_in[11];
    const float* b4  = (const float*)d_in[12];
    const float* Wg  = (const float*)d_in[13];
    const float* sg  = (const float*)d_in[14];
    const float* bg  = (const float*)d_in[15];
    const float* Ws1 = (const float*)d_in[16];
    const float* ss1 = (const float*)d_in[17];
    const float* bs1 = (const float*)d_in[18];
    const float* Ws2 = (const float*)d_in[19];
    const float* ss2 = (const float*)d_in[20];
    const float* bs2 = (const float*)d_in[21];
    const float* Ws3 = (const float*)d_in[22];
    const float* bs3 = (const float*)d_in[23];
    float* outp = (float*)d_out;

    float *dist, *xx, *xcat, *base, *wc, *act, *part, *gvec, *sterm, *h1, *h2;
    int* idxp;
    cudaGetSymbolAddress((void**)&dist,  g_dist);
    cudaGetSymbolAddress((void**)&idxp,  g_idx);
    cudaGetSymbolAddress((void**)&xx,    g_xx);
    cudaGetSymbolAddress((void**)&xcat,  g_xcat);
    cudaGetSymbolAddress((void**)&base,  g_base);
    cudaGetSymbolAddress((void**)&wc,    g_Wc);
    cudaGetSymbolAddress((void**)&act,   g_act);
    cudaGetSymbolAddress((void**)&part,  g_part);
    cudaGetSymbolAddress((void**)&gvec,  g_gvec);
    cudaGetSymbolAddress((void**)&sterm, g_sterm);
    cudaGetSymbolAddress((void**)&h1,    g_h1);
    cudaGetSymbolAddress((void**)&h2,    g_h2);

    // Layer 1 (kNN on raw xyz, C=3, O=64 -> xcat[:, 0:64])
    k_sqnorm<<<NB / 64, 64>>>(x, 3, 3, xx);
    k_dist<<<dim3(NPT / 128, NPT / 128, BATCH), 256>>>(x, 3, 3, xx, dist);
    k_topk<<<NB / 8, 256>>>(dist, idxp);
    k_edge1<<<NB, 64>>>(x, idxp, W1, s1, b1, xcat);

    // Layers 2-4
    edge_layer(xcat, 0,   64,  W2, s2, b2, 64,  64,  xx, dist, idxp, wc, base);
    edge_layer(xcat, 64,  64,  W3, s3, b3, 128, 128, xx, dist, idxp, wc, base);
    edge_layer(xcat, 128, 128, W4, s4, b4, 256, 256, xx, dist, idxp, wc, base);

    // Global feature: g = max_n lrelu(sg*(xcat.Wg^T)+bg)
    k_gemm<128><<<dim3(NB / 128, 1024 / 128), 256>>>(xcat, 512, Wg, 512, 512, 1024,
                                                     sg, bg, nullptr, act, 1024, 1);
    k_rowmax1<<<dim3(4, 32, BATCH), 256>>>(act, part);
    k_rowmax2<<<(BATCH * 1024 + 255) / 256, 256>>>(part, gvec);

    // Ws1: split [xcat ; g] -> GEMM on xcat + per-batch sterm from g
    k_sterm<<<BATCH * 512 * 32 / 256, 256>>>(Ws1, gvec, sterm);
    k_gemm<128><<<dim3(NB / 128, 512 / 128), 256>>>(xcat, 512, Ws1, 1536, 512, 512,
                                                    ss1, bs1, sterm, h1, 512, 1);
    // Ws2
    k_gemm<128><<<dim3(NB / 128, 256 / 128), 256>>>(h1, 512, Ws2, 512, 512, 256,
                                                    ss2, bs2, nullptr, h2, 256, 1);
    // Ws3 (13 classes) + bias
    k_out<<<NB / 256, 256>>>(h2, Ws3, bs3, outp);
}